// round 2
// baseline (speedup 1.0000x reference)
#include <cuda_runtime.h>

#define NN 100000
#define NE 1600000

// ---- scratch (static __device__ arrays; no allocation allowed) ----
__device__ int   g_is64;
__device__ int   g_src[NE];
__device__ int   g_dst[NE];
__device__ float g_deg[NN];
__device__ float g_agg1[NN * 64];
__device__ float g_h[NN * 64];
__device__ float g_p2[NN * 32];   // h @ Wl2 (aggregated in scatter2)
__device__ float g_r2[NN * 32];   // h @ Wr2 (root term)
__device__ float g_agg2[NN * 32];

// Detect int64 vs int32 edge_index: values are in [0, 100000), so if the
// buffer is int64 (little-endian) every odd 32-bit word (high half) is 0.
// If int32, odd words are random node ids (P(all 32 == 0) ~ 0).
__global__ void detect_kernel(const int* __restrict__ w) {
    int lane = threadIdx.x;
    int v = w[2 * lane + 1];
    unsigned m = __ballot_sync(0xffffffffu, v == 0);
    if (lane == 0) g_is64 = (m == 0xffffffffu) ? 1 : 0;
}

__global__ void convert_kernel(const void* __restrict__ e) {
    int i = blockIdx.x * blockDim.x + threadIdx.x;
    if (i >= NE) return;
    int s, d;
    if (g_is64) {
        const long long* p = (const long long*)e;
        s = (int)p[i];
        d = (int)p[NE + i];
    } else {
        const int* p = (const int*)e;
        s = p[i];
        d = p[NE + i];
    }
    g_src[i] = s;
    g_dst[i] = d;
}

__global__ void zero_kernel() {
    int i = blockIdx.x * blockDim.x + threadIdx.x;
    float4 z = make_float4(0.f, 0.f, 0.f, 0.f);
    if (i < NN * 16) ((float4*)g_agg1)[i] = z;   // 6.4M floats
    if (i < NN * 8)  ((float4*)g_agg2)[i] = z;   // 3.2M floats
    if (i < NN / 4)  ((float4*)g_deg)[i]  = z;   // 100k floats
}

// Scatter layer 1: agg1[dst] += x[src] (64 floats / edge), deg[dst] += 1.
// Thread = (edge, 16B chunk); 16 threads/edge -> coalesced 256B gather + red.
__global__ void __launch_bounds__(256) scatter1_kernel(const float* __restrict__ x) {
    int idx = blockIdx.x * 256 + threadIdx.x;
    int e = idx >> 4, c = idx & 15;
    if (e >= NE) return;
    int s = g_src[e], d = g_dst[e];
    float4 v = ((const float4*)x)[s * 16 + c];
    float* dst = g_agg1 + (size_t)d * 64 + c * 4;
    asm volatile("red.global.add.v4.f32 [%0], {%1,%2,%3,%4};"
                 :: "l"(dst), "f"(v.x), "f"(v.y), "f"(v.z), "f"(v.w)
                 : "memory");
    if (c == 0)
        asm volatile("red.global.add.f32 [%0], %1;"
                     :: "l"(g_deg + d), "f"(1.0f)
                     : "memory");
}

// Layer 1: h = relu((agg1 * inv_deg) @ Wl1 + x @ Wr1 + b1)
// inv_deg applied AFTER the agg dot product (scalar per node) to avoid prescaling.
// 256 thr: 16 nodes/tile x 16 j-groups (4 outputs each, float4 smem weight loads).
__global__ void __launch_bounds__(256) layer1_kernel(
    const float* __restrict__ x, const float* __restrict__ Wl,
    const float* __restrict__ Wr, const float* __restrict__ b) {
    __shared__ float sWl[64 * 64], sWr[64 * 64], sb[64];
    __shared__ float sA[16 * 64], sX[16 * 64];
    int tid = threadIdx.x;
    for (int i = tid; i < 4096; i += 256) { sWl[i] = Wl[i]; sWr[i] = Wr[i]; }
    if (tid < 64) sb[tid] = b[tid];
    int ln = tid >> 4, jt = tid & 15;
    __syncthreads();
    for (int tile = blockIdx.x; tile < NN / 16; tile += gridDim.x) {
        int base = tile * 16;
        __syncthreads();
        ((float4*)sA)[tid] = ((const float4*)g_agg1)[base * 16 + tid];
        ((float4*)sX)[tid] = ((const float4*)x)[base * 16 + tid];
        __syncthreads();
        float4 aA = make_float4(0.f, 0.f, 0.f, 0.f);
        float4 aX = make_float4(0.f, 0.f, 0.f, 0.f);
#pragma unroll
        for (int k = 0; k < 64; k++) {
            float a  = sA[ln * 64 + k];
            float xv = sX[ln * 64 + k];
            float4 wl = ((const float4*)sWl)[k * 16 + jt];
            float4 wr = ((const float4*)sWr)[k * 16 + jt];
            aA.x += a * wl.x;  aA.y += a * wl.y;  aA.z += a * wl.z;  aA.w += a * wl.w;
            aX.x += xv * wr.x; aX.y += xv * wr.y; aX.z += xv * wr.z; aX.w += xv * wr.w;
        }
        int n = base + ln;
        float inv = 1.f / fmaxf(g_deg[n], 1.f);
        float4 hv;
        hv.x = fmaxf(aA.x * inv + aX.x + sb[jt * 4 + 0], 0.f);
        hv.y = fmaxf(aA.y * inv + aX.y + sb[jt * 4 + 1], 0.f);
        hv.z = fmaxf(aA.z * inv + aX.z + sb[jt * 4 + 2], 0.f);
        hv.w = fmaxf(aA.w * inv + aX.w + sb[jt * 4 + 3], 0.f);
        ((float4*)g_h)[n * 16 + jt] = hv;
    }
}

// Pre-projection for layer 2 (linearity trick): p2 = h @ Wl2, r2 = h @ Wr2.
// Aggregating the 32-dim p2 halves edge traffic vs aggregating 64-dim h.
__global__ void __launch_bounds__(256) proj_kernel(
    const float* __restrict__ Wl2, const float* __restrict__ Wr2) {
    __shared__ float sWl[64 * 32], sWr[64 * 32];
    __shared__ float sH[32 * 64];
    int tid = threadIdx.x;
    for (int i = tid; i < 2048; i += 256) { sWl[i] = Wl2[i]; sWr[i] = Wr2[i]; }
    int ln = tid >> 3, jt = tid & 7;
    __syncthreads();
    for (int tile = blockIdx.x; tile < NN / 32; tile += gridDim.x) {
        int base = tile * 32;
        __syncthreads();
        ((float4*)sH)[tid]       = ((const float4*)g_h)[base * 16 + tid];
        ((float4*)sH)[tid + 256] = ((const float4*)g_h)[base * 16 + tid + 256];
        __syncthreads();
        float4 aP = make_float4(0.f, 0.f, 0.f, 0.f);
        float4 aR = make_float4(0.f, 0.f, 0.f, 0.f);
#pragma unroll
        for (int k = 0; k < 64; k++) {
            float hv = sH[ln * 64 + k];
            float4 wl = ((const float4*)sWl)[k * 8 + jt];
            float4 wr = ((const float4*)sWr)[k * 8 + jt];
            aP.x += hv * wl.x; aP.y += hv * wl.y; aP.z += hv * wl.z; aP.w += hv * wl.w;
            aR.x += hv * wr.x; aR.y += hv * wr.y; aR.z += hv * wr.z; aR.w += hv * wr.w;
        }
        int n = base + ln;
        ((float4*)g_p2)[n * 8 + jt] = aP;
        ((float4*)g_r2)[n * 8 + jt] = aR;
    }
}

// Scatter layer 2: agg2[dst] += p2[src] (32 floats / edge).
__global__ void __launch_bounds__(256) scatter2_kernel() {
    int idx = blockIdx.x * 256 + threadIdx.x;
    int e = idx >> 3, c = idx & 7;
    if (e >= NE) return;
    int s = g_src[e], d = g_dst[e];
    float4 v = ((const float4*)g_p2)[s * 8 + c];
    float* dst = g_agg2 + (size_t)d * 32 + c * 4;
    asm volatile("red.global.add.v4.f32 [%0], {%1,%2,%3,%4};"
                 :: "l"(dst), "f"(v.x), "f"(v.y), "f"(v.z), "f"(v.w)
                 : "memory");
}

// Final: h2 = agg2*inv + r2 + b2 (write to out), then trust head
// (32->16 relu -> 16->1 sigmoid) warp-per-node via shuffles.
__global__ void __launch_bounds__(256) final_kernel(
    const float* __restrict__ b2, const float* __restrict__ Wt1,
    const float* __restrict__ bt1, const float* __restrict__ Wt2,
    const float* __restrict__ bt2, float* __restrict__ out) {
    __shared__ float sW1[32 * 16], sB2[32], sBt1[16], sW2[16];
    __shared__ float sBt2;
    int tid = threadIdx.x;
    sW1[tid] = Wt1[tid];
    sW1[tid + 256] = Wt1[tid + 256];
    if (tid < 32) sB2[tid] = b2[tid];
    if (tid < 16) { sBt1[tid] = bt1[tid]; sW2[tid] = Wt2[tid]; }
    if (tid == 0) sBt2 = bt2[0];
    __syncthreads();
    int warp = tid >> 5, lane = tid & 31;
    int n = blockIdx.x * 8 + warp;   // 12500 * 8 == 100000 exactly
    float inv = 1.f / fmaxf(g_deg[n], 1.f);
    float v = g_agg2[n * 32 + lane] * inv + g_r2[n * 32 + lane] + sB2[lane];
    out[n * 32 + lane] = v;
    float acc = (lane < 16) ? sBt1[lane] : 0.f;
    int o = lane & 15;
#pragma unroll
    for (int j = 0; j < 32; j++) {
        float hv = __shfl_sync(0xffffffffu, v, j);
        acc += hv * sW1[j * 16 + o];
    }
    float t = fmaxf(acc, 0.f) * sW2[o];
    t += __shfl_down_sync(0xffffffffu, t, 8);
    t += __shfl_down_sync(0xffffffffu, t, 4);
    t += __shfl_down_sync(0xffffffffu, t, 2);
    t += __shfl_down_sync(0xffffffffu, t, 1);
    if (lane == 0)
        out[NN * 32 + n] = 1.f / (1.f + __expf(-(t + sBt2)));
}

extern "C" void kernel_launch(void* const* d_in, const int* in_sizes, int n_in,
                              void* d_out, int out_size) {
    const float* x   = (const float*)d_in[0];
    const void*  ei  = d_in[1];
    const float* Wl1 = (const float*)d_in[2];
    const float* Wr1 = (const float*)d_in[3];
    const float* b1  = (const float*)d_in[4];
    const float* Wl2 = (const float*)d_in[5];
    const float* Wr2 = (const float*)d_in[6];
    const float* b2  = (const float*)d_in[7];
    const float* Wt1 = (const float*)d_in[8];
    const float* bt1 = (const float*)d_in[9];
    const float* Wt2 = (const float*)d_in[10];
    const float* bt2 = (const float*)d_in[11];
    float* out = (float*)d_out;

    detect_kernel<<<1, 32>>>((const int*)ei);
    convert_kernel<<<(NE + 255) / 256, 256>>>(ei);
    zero_kernel<<<(NN * 16 + 255) / 256, 256>>>();
    scatter1_kernel<<<NE * 16 / 256, 256>>>(x);
    layer1_kernel<<<740, 256>>>(x, Wl1, Wr1, b1);
    proj_kernel<<<740, 256>>>(Wl2, Wr2);
    scatter2_kernel<<<NE * 8 / 256, 256>>>();
    final_kernel<<<NN / 8, 256>>>(b2, Wt1, bt1, Wt2, bt2, out);
}